// round 1
// baseline (speedup 1.0000x reference)
#include <cuda_runtime.h>
#include <math.h>

#define NN 100000
#define EE 1600000
#define NCAND 10000
#define GG 1000
#define ND 32
#define ED 8
#define LL 4

// Scratch (static device globals — no runtime allocation)
__device__ float g_h[NN * ND];      // node embeddings       12.8 MB
__device__ float g_hs[NN * ED];     // h @ Ws + be            3.2 MB
__device__ float g_hd[NN * ED];     // h @ Wd                 3.2 MB
__device__ float g_agg[NN * ED];    // segment_sum target     3.2 MB
__device__ float g_e[EE * ED];      // edge embeddings       51.2 MB
__device__ float g_logits[NCAND];
__device__ int   g_seg[NCAND];
__device__ float g_mx[GG];
__device__ float g_sum[GG];

__global__ void k_init_h(const float* __restrict__ x,
                         const float* __restrict__ Wn,
                         const float* __restrict__ bn) {
    int t = blockIdx.x * blockDim.x + threadIdx.x;
    if (t >= NN * ND) return;
    int n = t >> 5, c = t & 31;
    g_h[t] = fmaf(x[2 * n], Wn[c], fmaf(x[2 * n + 1], Wn[ND + c], bn[c]));
}

__global__ void k_init_e(const float* __restrict__ ea,
                         const float* __restrict__ We,
                         const float* __restrict__ be) {
    int t = blockIdx.x * blockDim.x + threadIdx.x;
    if (t >= EE * ED) return;
    int i = t >> 3, c = t & 7;
    g_e[t] = fmaf(ea[i], We[c], be[c]);
}

// Per-node precompute: hs = h@Ws + be, hd = h@Wd; also zero agg.
__global__ void k_pre(const float* __restrict__ Wel,
                      const float* __restrict__ bel, int l) {
    __shared__ float sW[2 * ND * ED];   // rows 0..63 of We_l[l]
    __shared__ float sb[ED];
    const float* W = Wel + l * (2 * ND + ED) * ED;
    for (int i = threadIdx.x; i < 2 * ND * ED; i += blockDim.x) sW[i] = W[i];
    if (threadIdx.x < ED) sb[threadIdx.x] = bel[l * ED + threadIdx.x];
    __syncthreads();
    int t = blockIdx.x * blockDim.x + threadIdx.x;
    if (t >= NN * ED) return;
    int n = t >> 3, j = t & 7;
    const float* hrow = &g_h[n * ND];
    float accs = sb[j], accd = 0.f;
#pragma unroll
    for (int i = 0; i < ND; i++) {
        float hv = hrow[i];
        accs = fmaf(hv, sW[i * ED + j], accs);
        accd = fmaf(hv, sW[(ND + i) * ED + j], accd);
    }
    g_hs[t] = accs;
    g_hd[t] = accd;
    g_agg[t] = 0.f;
}

// Per-edge: new_e = relu(hs[src] + hd[dst] + e@We), agg[dst]+=new_e, e+=new_e
__global__ void k_edge(const int* __restrict__ ei,
                       const float* __restrict__ Wel, int l) {
    __shared__ float sW[ED * ED];
    if (threadIdx.x < ED * ED)
        sW[threadIdx.x] = Wel[l * (2 * ND + ED) * ED + 2 * ND * ED + threadIdx.x];
    __syncthreads();
    int e = blockIdx.x * blockDim.x + threadIdx.x;
    if (e >= EE) return;
    int src = ei[e], dst = ei[EE + e];
    const float4* ep = (const float4*)&g_e[e * ED];
    float4 e0 = ep[0], e1 = ep[1];
    const float4* sp = (const float4*)&g_hs[src * ED];
    float4 s0 = sp[0], s1 = sp[1];
    const float4* dp = (const float4*)&g_hd[dst * ED];
    float4 d0 = dp[0], d1 = dp[1];
    float ein[8] = {e0.x, e0.y, e0.z, e0.w, e1.x, e1.y, e1.z, e1.w};
    float base[8] = {s0.x + d0.x, s0.y + d0.y, s0.z + d0.z, s0.w + d0.w,
                     s1.x + d1.x, s1.y + d1.y, s1.z + d1.z, s1.w + d1.w};
    float ne[8];
#pragma unroll
    for (int j = 0; j < 8; j++) {
        float acc = base[j];
#pragma unroll
        for (int i = 0; i < 8; i++) acc = fmaf(ein[i], sW[i * ED + j], acc);
        ne[j] = fmaxf(acc, 0.f);
    }
    float* ap = &g_agg[dst * ED];
    asm volatile("red.global.add.v4.f32 [%0], {%1,%2,%3,%4};"
                 :: "l"(ap), "f"(ne[0]), "f"(ne[1]), "f"(ne[2]), "f"(ne[3]) : "memory");
    asm volatile("red.global.add.v4.f32 [%0], {%1,%2,%3,%4};"
                 :: "l"(ap + 4), "f"(ne[4]), "f"(ne[5]), "f"(ne[6]), "f"(ne[7]) : "memory");
    float4* eo = (float4*)&g_e[e * ED];
    eo[0] = make_float4(ein[0] + ne[0], ein[1] + ne[1], ein[2] + ne[2], ein[3] + ne[3]);
    eo[1] = make_float4(ein[4] + ne[4], ein[5] + ne[5], ein[6] + ne[6], ein[7] + ne[7]);
}

// Warp per node: lane = output column. new_h = relu([h,agg]@Wn + bn); h += new_h
__global__ void k_node(const float* __restrict__ Wnl,
                       const float* __restrict__ bnl, int l) {
    __shared__ float sW[(ND + ED) * ND];   // 40x32
    __shared__ float sb[ND];
    for (int i = threadIdx.x; i < (ND + ED) * ND; i += blockDim.x)
        sW[i] = Wnl[l * (ND + ED) * ND + i];
    if (threadIdx.x < ND) sb[threadIdx.x] = bnl[l * ND + threadIdx.x];
    __syncthreads();
    int warp = (blockIdx.x * blockDim.x + threadIdx.x) >> 5;
    int lane = threadIdx.x & 31;
    if (warp >= NN) return;
    float hv = g_h[warp * ND + lane];
    float av = (lane < ED) ? g_agg[warp * ED + lane] : 0.f;
    float acc = sb[lane];
#pragma unroll
    for (int i = 0; i < ND; i++)
        acc = fmaf(__shfl_sync(0xffffffffu, hv, i), sW[i * ND + lane], acc);
#pragma unroll
    for (int i = 0; i < ED; i++)
        acc = fmaf(__shfl_sync(0xffffffffu, av, i), sW[(ND + i) * ND + lane], acc);
    acc = fmaxf(acc, 0.f);
    g_h[warp * ND + lane] = hv + acc;
}

__global__ void k_finit() {
    int t = blockIdx.x * blockDim.x + threadIdx.x;
    if (t < GG) { g_mx[t] = -INFINITY; g_sum[t] = 0.f; }
}

__global__ void k_logits(const int* __restrict__ cand,
                         const int* __restrict__ batch,
                         const float* __restrict__ Wout,
                         const float* __restrict__ bout) {
    int c = blockIdx.x * blockDim.x + threadIdx.x;
    if (c >= NCAND) return;
    int n = cand[c];
    float acc = bout[0];
    const float* hrow = &g_h[n * ND];
#pragma unroll
    for (int i = 0; i < ND; i++) acc = fmaf(hrow[i], Wout[i], acc);
    g_logits[c] = acc;
    int s = batch[n];
    g_seg[c] = s;
    // order-preserving float atomic max
    if (acc >= 0.f) atomicMax((int*)&g_mx[s], __float_as_int(acc));
    else            atomicMin((unsigned int*)&g_mx[s], __float_as_uint(acc));
}

__global__ void k_sumexp() {
    int c = blockIdx.x * blockDim.x + threadIdx.x;
    if (c >= NCAND) return;
    int s = g_seg[c];
    float sh = g_logits[c] - g_mx[s];
    g_logits[c] = sh;
    atomicAdd(&g_sum[s], expf(sh));
}

__global__ void k_out(float* __restrict__ out) {
    int c = blockIdx.x * blockDim.x + threadIdx.x;
    if (c >= NCAND) return;
    out[c] = g_logits[c] - logf(g_sum[g_seg[c]]);
}

extern "C" void kernel_launch(void* const* d_in, const int* in_sizes, int n_in,
                              void* d_out, int out_size) {
    const float* x         = (const float*)d_in[0];
    const float* edge_attr = (const float*)d_in[1];
    const float* Wn_in     = (const float*)d_in[2];
    const float* bn_in     = (const float*)d_in[3];
    const float* We_in     = (const float*)d_in[4];
    const float* be_in     = (const float*)d_in[5];
    const float* We_l      = (const float*)d_in[6];
    const float* be_l      = (const float*)d_in[7];
    const float* Wn_l      = (const float*)d_in[8];
    const float* bn_l      = (const float*)d_in[9];
    const float* Wout      = (const float*)d_in[10];
    const float* bout      = (const float*)d_in[11];
    const int* edge_index  = (const int*)d_in[12];
    const int* batch       = (const int*)d_in[13];
    const int* cand        = (const int*)d_in[14];
    float* out = (float*)d_out;

    k_init_h<<<(NN * ND + 255) / 256, 256>>>(x, Wn_in, bn_in);
    k_init_e<<<(EE * ED + 255) / 256, 256>>>(edge_attr, We_in, be_in);
    for (int l = 0; l < LL; l++) {
        k_pre<<<(NN * ED + 255) / 256, 256>>>(We_l, be_l, l);
        k_edge<<<(EE + 255) / 256, 256>>>(edge_index, We_l, l);
        k_node<<<(NN * ND + 255) / 256, 256>>>(Wn_l, bn_l, l);
    }
    k_finit<<<(GG + 255) / 256, 256>>>();
    k_logits<<<(NCAND + 255) / 256, 256>>>(cand, batch, Wout, bout);
    k_sumexp<<<(NCAND + 255) / 256, 256>>>();
    k_out<<<(NCAND + 255) / 256, 256>>>(out);
}